// round 3
// baseline (speedup 1.0000x reference)
#include <cuda_runtime.h>

#define NN 524288
#define ROWS_PB 64
#define GRID (NN / ROWS_PB)   // 8192
#define DD 64
#define HH 128
#define EE 8
#define AA 18
#define BN_EPS 1e-5f

typedef unsigned long long u64;

__device__ __forceinline__ u64 pk2(float lo, float hi) {
    u64 r; asm("mov.b64 %0,{%1,%2};" : "=l"(r) : "f"(lo), "f"(hi)); return r;
}
__device__ __forceinline__ void upk2(u64 v, float& lo, float& hi) {
    asm("mov.b64 {%0,%1},%2;" : "=f"(lo), "=f"(hi) : "l"(v));
}
__device__ __forceinline__ void ffma2(u64& d, u64 a, u64 b) {
    asm("fma.rn.f32x2 %0,%1,%2,%0;" : "+l"(d) : "l"(a), "l"(b));
}
__device__ __forceinline__ u64 add2(u64 a, u64 b) {
    u64 r; asm("add.rn.f32x2 %0,%1,%2;" : "=l"(r) : "l"(a), "l"(b)); return r;
}

// ---- smem layout (float offsets) ----
#define W1S_OFF   0        // [64][132] k-major W1, size 8448
#define XS_OFF    8448     // [64][68]  k-major X tile, size 4352
#define SCALE_OFF 12800    // [128]
#define BIAS_OFF  12928    // [128]
#define W2T_OFF   13056    // [128][8]  w2t[j][e]
#define B2S_OFF   14080    // [8] (pad 16)
#define WES_OFF   14096    // [8][18][68] padded, size 9824
#define INT_OFF   23920    // best[64], cnt[8], base[8], cnt2[8], order[64]
#define SMEM_FLOATS 24080
#define WE_A_STRIDE 68
#define WE_E_STRIDE 1228   // 18*68 + 4

__global__ __launch_bounds__(256, 2) void moe_fused(
    const float* __restrict__ X,  const float* __restrict__ W1, const float* __restrict__ b1,
    const float* __restrict__ gamma, const float* __restrict__ beta,
    const float* __restrict__ rmean, const float* __restrict__ rvar,
    const float* __restrict__ W2, const float* __restrict__ b2, const float* __restrict__ We,
    float* __restrict__ out, float* __restrict__ ret)
{
    extern __shared__ float sm[];
    int* best_s  = (int*)(sm + INT_OFF);        // [64]
    int* cnt_s   = (int*)(sm + INT_OFF + 64);   // [8]
    int* base_s  = (int*)(sm + INT_OFF + 72);   // [8]
    int* cnt2_s  = (int*)(sm + INT_OFF + 80);   // [8]
    int* order_s = (int*)(sm + INT_OFF + 88);   // [64]

    const int tid = threadIdx.x;
    const int row0 = blockIdx.x * ROWS_PB;

    // ================= staging =================
    {   // W1 [128j][64k] -> W1s[k][j] stride 132. lanes vary j -> conflict-free STS.
        const float4* w1f4 = (const float4*)W1;
        #pragma unroll
        for (int i = 0; i < 8; i++) {
            int idx = i * 256 + tid;
            int j = idx & 127, kq = idx >> 7;
            float4 v = w1f4[j * 16 + kq];
            sm[W1S_OFF + (4 * kq + 0) * 132 + j] = v.x;
            sm[W1S_OFF + (4 * kq + 1) * 132 + j] = v.y;
            sm[W1S_OFF + (4 * kq + 2) * 132 + j] = v.z;
            sm[W1S_OFF + (4 * kq + 3) * 132 + j] = v.w;
        }
    }
    {   // X tile [64r][64k] -> Xs[k][r] stride 68. lanes vary r -> conflict-free.
        const float4* xf4 = (const float4*)X;
        #pragma unroll
        for (int i = 0; i < 4; i++) {
            int idx = i * 256 + tid;
            int r = idx & 63, kq = idx >> 6;
            float4 v = xf4[(size_t)(row0 + r) * 16 + kq];
            sm[XS_OFF + (4 * kq + 0) * 68 + r] = v.x;
            sm[XS_OFF + (4 * kq + 1) * 68 + r] = v.y;
            sm[XS_OFF + (4 * kq + 2) * 68 + r] = v.z;
            sm[XS_OFF + (4 * kq + 3) * 68 + r] = v.w;
        }
    }
    {   // We [8e][18a][64k] -> padded [e][a][68]
        const float4* wef4 = (const float4*)We;
        float4* wes4 = (float4*)(sm + WES_OFF);
        #pragma unroll
        for (int i = 0; i < 9; i++) {
            int idx = i * 256 + tid;   // < 2304
            int e = idx / 288, rem = idx % 288;
            int a = rem >> 4, kq = rem & 15;
            wes4[e * 307 + a * 17 + kq] = wef4[idx];
        }
    }
    // W2 transpose
    #pragma unroll
    for (int i = 0; i < 4; i++) {
        int idx = i * 256 + tid;
        int j = idx >> 3, e = idx & 7;
        sm[W2T_OFF + idx] = W2[e * HH + j];
    }
    if (tid < HH) {
        float s = gamma[tid] * rsqrtf(rvar[tid] + BN_EPS);
        sm[SCALE_OFF + tid] = s;
        sm[BIAS_OFF + tid]  = s * (b1[tid] - rmean[tid]) + beta[tid];
    }
    if (tid < EE) sm[B2S_OFF + tid] = b2[tid];
    if (tid < EE) { cnt_s[tid] = 0; cnt2_s[tid] = 0; }
    __syncthreads();

    // ================= gating GEMM =================
    const int tc = tid & 31;     // j-tile index (4 j's each)
    const int w  = tid >> 5;     // warp id = row-group (8 rows)

    const u64 Z = pk2(0.f, 0.f);
    u64 acc[4][4];               // [row-pair][j]
    #pragma unroll
    for (int p = 0; p < 4; p++)
        #pragma unroll
        for (int j = 0; j < 4; j++) acc[p][j] = Z;

    #pragma unroll 8
    for (int k = 0; k < DD; k++) {
        ulonglong2 xa = *(const ulonglong2*)(sm + XS_OFF + k * 68 + w * 8);     // rows 0-3 (2 pairs)
        ulonglong2 xb = *(const ulonglong2*)(sm + XS_OFF + k * 68 + w * 8 + 4); // rows 4-7
        float4 wv = *(const float4*)(sm + W1S_OFF + k * 132 + tc * 4);
        u64 w0 = pk2(wv.x, wv.x), w1v = pk2(wv.y, wv.y);
        u64 w2v = pk2(wv.z, wv.z), w3 = pk2(wv.w, wv.w);
        ffma2(acc[0][0], xa.x, w0); ffma2(acc[1][0], xa.y, w0);
        ffma2(acc[2][0], xb.x, w0); ffma2(acc[3][0], xb.y, w0);
        ffma2(acc[0][1], xa.x, w1v); ffma2(acc[1][1], xa.y, w1v);
        ffma2(acc[2][1], xb.x, w1v); ffma2(acc[3][1], xb.y, w1v);
        ffma2(acc[0][2], xa.x, w2v); ffma2(acc[1][2], xa.y, w2v);
        ffma2(acc[2][2], xb.x, w2v); ffma2(acc[3][2], xb.y, w2v);
        ffma2(acc[0][3], xa.x, w3); ffma2(acc[1][3], xa.y, w3);
        ffma2(acc[2][3], xb.x, w3); ffma2(acc[3][3], xb.y, w3);
    }

    // ================= epilogue: BN+ReLU + partial logits =================
    u64 plog[8][4];   // [row 0..7][e-pair 0..3]
    #pragma unroll
    for (int r = 0; r < 8; r++)
        #pragma unroll
        for (int e = 0; e < 4; e++) plog[r][e] = Z;

    #pragma unroll
    for (int j = 0; j < 4; j++) {
        int jg = tc * 4 + j;
        float s = sm[SCALE_OFF + jg];
        float b = sm[BIAS_OFF + jg];
        u64 s2 = pk2(s, s), bb = pk2(b, b);
        ulonglong2 wq0 = *(const ulonglong2*)(sm + W2T_OFF + jg * 8);
        ulonglong2 wq1 = *(const ulonglong2*)(sm + W2T_OFF + jg * 8 + 4);
        #pragma unroll
        for (int p = 0; p < 4; p++) {
            u64 h2 = bb;
            ffma2(h2, acc[p][j], s2);
            float h0, h1; upk2(h2, h0, h1);
            h0 = fmaxf(h0, 0.f); h1 = fmaxf(h1, 0.f);
            u64 h0b = pk2(h0, h0), h1b = pk2(h1, h1);
            ffma2(plog[2 * p][0], h0b, wq0.x);
            ffma2(plog[2 * p][1], h0b, wq0.y);
            ffma2(plog[2 * p][2], h0b, wq1.x);
            ffma2(plog[2 * p][3], h0b, wq1.y);
            ffma2(plog[2 * p + 1][0], h1b, wq0.x);
            ffma2(plog[2 * p + 1][1], h1b, wq0.y);
            ffma2(plog[2 * p + 1][2], h1b, wq1.x);
            ffma2(plog[2 * p + 1][3], h1b, wq1.y);
        }
    }

    // ---- butterfly reduce across 32 lanes ----
    #pragma unroll
    for (int off = 16; off >= 1; off >>= 1) {
        #pragma unroll
        for (int r = 0; r < 8; r++)
            #pragma unroll
            for (int e = 0; e < 4; e++) {
                u64 o = __shfl_xor_sync(0xffffffffu, plog[r][e], off);
                plog[r][e] = add2(plog[r][e], o);
            }
    }

    // ---- argmax + one-hot + counting (lanes 0..7) ----
    if (tc < 8) {
        int r = tc;
        ulonglong2 b2a = *(const ulonglong2*)(sm + B2S_OFF);
        ulonglong2 b2bq = *(const ulonglong2*)(sm + B2S_OFF + 4);
        u64 l0 = add2(plog[r][0], b2a.x);
        u64 l1 = add2(plog[r][1], b2a.y);
        u64 l2 = add2(plog[r][2], b2bq.x);
        u64 l3 = add2(plog[r][3], b2bq.y);
        float lf[8];
        upk2(l0, lf[0], lf[1]); upk2(l1, lf[2], lf[3]);
        upk2(l2, lf[4], lf[5]); upk2(l3, lf[6], lf[7]);
        int best = 0; float bv = lf[0];
        #pragma unroll
        for (int e = 1; e < 8; e++) if (lf[e] > bv) { bv = lf[e]; best = e; }

        int lrow = w * 8 + r;
        int grow = row0 + lrow;
        float rr[8];
        #pragma unroll
        for (int e = 0; e < 8; e++) rr[e] = (e == best) ? 1.0f : 0.0f;
        float4* pr = (float4*)(ret + (size_t)grow * EE);
        pr[0] = make_float4(rr[0], rr[1], rr[2], rr[3]);
        pr[1] = make_float4(rr[4], rr[5], rr[6], rr[7]);

        best_s[lrow] = best;
        atomicAdd(&cnt_s[best], 1);
    }
    __syncthreads();

    if (tid == 0) {
        int acc0 = 0;
        #pragma unroll
        for (int e = 0; e < 8; e++) { base_s[e] = acc0; acc0 += cnt_s[e]; }
    }
    __syncthreads();
    if (tid < ROWS_PB) {
        int e = best_s[tid];
        int pos = atomicAdd(&cnt2_s[e], 1);
        order_s[base_s[e] + pos] = tid;
    }
    __syncthreads();

    // ================= expert GEMV (rows grouped by expert) =================
    {
        int lane = tc;
        int lrow = order_s[w * 8 + (lane & 7)];
        int part = lane >> 3;                  // 0..3
        int grow = row0 + lrow;
        int best = best_s[lrow];

        // load x row (global, L2) into packed pairs
        u64 xp[32];
        const ulonglong2* xg = (const ulonglong2*)(X + (size_t)grow * DD);
        #pragma unroll
        for (int i = 0; i < 16; i++) {
            ulonglong2 v = xg[i];
            xp[2 * i] = v.x; xp[2 * i + 1] = v.y;
        }

        const float* wep = sm + WES_OFF + best * WE_E_STRIDE;
        int aStart = (part < 2) ? part * 5 : 10 + (part - 2) * 4;
        int aCnt   = (part < 2) ? 5 : 4;
        float* orow = out + (size_t)grow * AA;

        for (int ai = 0; ai < aCnt; ai++) {
            int a = aStart + ai;
            const ulonglong2* pw = (const ulonglong2*)(wep + a * WE_A_STRIDE);
            u64 a0 = Z, a1 = Z, a2 = Z, a3 = Z;
            #pragma unroll
            for (int m = 0; m < 8; m++) {
                ulonglong2 q0 = pw[2 * m];
                ulonglong2 q1 = pw[2 * m + 1];
                ffma2(a0, q0.x, xp[4 * m + 0]);
                ffma2(a1, q0.y, xp[4 * m + 1]);
                ffma2(a2, q1.x, xp[4 * m + 2]);
                ffma2(a3, q1.y, xp[4 * m + 3]);
            }
            u64 s = add2(add2(a0, a1), add2(a2, a3));
            float lo, hi; upk2(s, lo, hi);
            orow[a] = lo + hi;
        }
    }
}

extern "C" void kernel_launch(void* const* d_in, const int* in_sizes, int n_in,
                              void* d_out, int out_size) {
    const float* X     = (const float*)d_in[0];
    const float* W1    = (const float*)d_in[1];
    const float* b1    = (const float*)d_in[2];
    const float* gamma = (const float*)d_in[3];
    const float* beta  = (const float*)d_in[4];
    const float* rmean = (const float*)d_in[5];
    const float* rvar  = (const float*)d_in[6];
    const float* W2    = (const float*)d_in[7];
    const float* b2    = (const float*)d_in[8];
    const float* We    = (const float*)d_in[9];

    float* out = (float*)d_out;                    // [N, A]
    float* ret = out + (size_t)NN * AA;            // [N, E]

    size_t smem = SMEM_FLOATS * sizeof(float);
    static bool attr_set = false;
    if (!attr_set) {
        cudaFuncSetAttribute(moe_fused, cudaFuncAttributeMaxDynamicSharedMemorySize, (int)smem);
        attr_set = true;
    }
    moe_fused<<<GRID, 256, smem>>>(X, W1, b1, gamma, beta, rmean, rvar, W2, b2, We, out, ret);
}

// round 4
// speedup vs baseline: 1.2005x; 1.2005x over previous
#include <cuda_runtime.h>

#define NN 524288
#define ROWS_PB 128
#define GRID (NN / ROWS_PB)   // 4096
#define DD 64
#define HH 128
#define EE 8
#define AA 18
#define BN_EPS 1e-5f

typedef unsigned long long u64;

__device__ __forceinline__ u64 pk2(float lo, float hi) {
    u64 r; asm("mov.b64 %0,{%1,%2};" : "=l"(r) : "f"(lo), "f"(hi)); return r;
}
__device__ __forceinline__ void upk2(u64 v, float& lo, float& hi) {
    asm("mov.b64 {%0,%1},%2;" : "=f"(lo), "=f"(hi) : "l"(v));
}
__device__ __forceinline__ void ffma2(u64& d, u64 a, u64 b) {
    asm("fma.rn.f32x2 %0,%1,%2,%0;" : "+l"(d) : "l"(a), "l"(b));
}
__device__ __forceinline__ u64 add2(u64 a, u64 b) {
    u64 r; asm("add.rn.f32x2 %0,%1,%2;" : "=l"(r) : "l"(a), "l"(b)); return r;
}

// ---- smem layout (float offsets) ----
// W1s: [64 k][16 jgrp * 12]    (8 floats used per grp, stride 12 for banks)
#define W1S_OFF   0
#define W1S_KSTR  192
// Xs:  [64 k][128 r + 4 pad]
#define XS_OFF    12288
#define XS_KSTR   132
// w2t: 16 jgrp * 68  (8 j * 8 e per grp + 4 pad)
#define W2T_OFF   20736
// sb:  16 jgrp * 20  (8 j * (scale,bias) + 4 pad)
#define SB_OFF    21824
#define B2S_OFF   22144   // 8 + pad
// wes: [8 e][18 a][68]
#define WES_OFF   22160
#define WE_A_STRIDE 68
#define WE_E_STRIDE 1228
#define BEST_OFF  31984   // 128 ints
#define SMEM_FLOATS 32112

__global__ __launch_bounds__(256, 1) void moe_fused(
    const float* __restrict__ X,  const float* __restrict__ W1, const float* __restrict__ b1,
    const float* __restrict__ gamma, const float* __restrict__ beta,
    const float* __restrict__ rmean, const float* __restrict__ rvar,
    const float* __restrict__ W2, const float* __restrict__ b2, const float* __restrict__ We,
    float* __restrict__ out, float* __restrict__ ret)
{
    extern __shared__ float sm[];
    int* best_s = (int*)(sm + BEST_OFF);

    const int tid = threadIdx.x;
    const int row0 = blockIdx.x * ROWS_PB;

    // ================= staging =================
    {   // W1 [128j][64k] -> W1s[k][grouped j]
        const float4* w1f4 = (const float4*)W1;
        #pragma unroll
        for (int i = 0; i < 8; i++) {
            int idx = i * 256 + tid;               // < 2048
            int j = idx & 127, kq = idx >> 7;
            float4 v = w1f4[j * 16 + kq];
            int jo = (j >> 3) * 12 + (j & 7);
            sm[W1S_OFF + (4 * kq + 0) * W1S_KSTR + jo] = v.x;
            sm[W1S_OFF + (4 * kq + 1) * W1S_KSTR + jo] = v.y;
            sm[W1S_OFF + (4 * kq + 2) * W1S_KSTR + jo] = v.z;
            sm[W1S_OFF + (4 * kq + 3) * W1S_KSTR + jo] = v.w;
        }
    }
    {   // X tile [128r][64k] -> Xs[k][r]
        const float4* xf4 = (const float4*)X;
        #pragma unroll
        for (int i = 0; i < 8; i++) {
            int idx = i * 256 + tid;               // < 2048
            int r = idx & 127, kq = idx >> 7;
            float4 v = xf4[(size_t)(row0 + r) * 16 + kq];
            sm[XS_OFF + (4 * kq + 0) * XS_KSTR + r] = v.x;
            sm[XS_OFF + (4 * kq + 1) * XS_KSTR + r] = v.y;
            sm[XS_OFF + (4 * kq + 2) * XS_KSTR + r] = v.z;
            sm[XS_OFF + (4 * kq + 3) * XS_KSTR + r] = v.w;
        }
    }
    {   // We [8e][18a][64k] -> padded [e][a][68]
        const float4* wef4 = (const float4*)We;
        float4* wes4 = (float4*)(sm + WES_OFF);
        #pragma unroll
        for (int i = 0; i < 9; i++) {
            int idx = i * 256 + tid;               // < 2304
            int e = idx / 288, rem = idx % 288;
            int a = rem >> 4, kq = rem & 15;
            wes4[e * 307 + a * 17 + kq] = wef4[idx];
        }
    }
    // W2 transpose into grouped layout
    #pragma unroll
    for (int i = 0; i < 4; i++) {
        int idx = i * 256 + tid;                   // < 1024
        int j = idx >> 3, e = idx & 7;
        sm[W2T_OFF + (j >> 3) * 68 + (j & 7) * 8 + e] = W2[e * HH + j];
    }
    if (tid < HH) {
        int j = tid;
        float s = gamma[j] * rsqrtf(rvar[j] + BN_EPS);
        int o = SB_OFF + (j >> 3) * 20 + (j & 7) * 2;
        sm[o]     = s;
        sm[o + 1] = s * (b1[j] - rmean[j]) + beta[j];
    }
    if (tid < EE) sm[B2S_OFF + tid] = b2[tid];
    __syncthreads();

    // ================= gating GEMM: thread tile 8 rows x 8 j =================
    const int tx = tid & 15;      // j-group (8 j)
    const int ty = tid >> 4;      // row-group (8 rows)

    const u64 Z = pk2(0.f, 0.f);
    u64 acc[4][8];                // [row-pair][j]
    #pragma unroll
    for (int p = 0; p < 4; p++)
        #pragma unroll
        for (int j = 0; j < 8; j++) acc[p][j] = Z;

    const float* xsb  = sm + XS_OFF + ty * 8;
    const float* w1b  = sm + W1S_OFF + tx * 12;

    #pragma unroll 4
    for (int k = 0; k < DD; k++) {
        ulonglong2 xa = *(const ulonglong2*)(xsb + k * XS_KSTR);       // rows 0-3
        ulonglong2 xb = *(const ulonglong2*)(xsb + k * XS_KSTR + 4);   // rows 4-7
        float4 wv0 = *(const float4*)(w1b + k * W1S_KSTR);
        float4 wv1 = *(const float4*)(w1b + k * W1S_KSTR + 4);
        u64 wd[8];
        wd[0] = pk2(wv0.x, wv0.x); wd[1] = pk2(wv0.y, wv0.y);
        wd[2] = pk2(wv0.z, wv0.z); wd[3] = pk2(wv0.w, wv0.w);
        wd[4] = pk2(wv1.x, wv1.x); wd[5] = pk2(wv1.y, wv1.y);
        wd[6] = pk2(wv1.z, wv1.z); wd[7] = pk2(wv1.w, wv1.w);
        #pragma unroll
        for (int j = 0; j < 8; j++) {
            ffma2(acc[0][j], xa.x, wd[j]);
            ffma2(acc[1][j], xa.y, wd[j]);
            ffma2(acc[2][j], xb.x, wd[j]);
            ffma2(acc[3][j], xb.y, wd[j]);
        }
    }

    // ================= epilogue: BN+ReLU + partial logits =================
    u64 v[32];                    // plog[row r][e-pair] = v[r*4+ep]
    #pragma unroll
    for (int i = 0; i < 32; i++) v[i] = Z;

    #pragma unroll
    for (int j = 0; j < 8; j++) {
        float2 sb2 = *(const float2*)(sm + SB_OFF + tx * 20 + j * 2);
        u64 s2 = pk2(sb2.x, sb2.x), bb = pk2(sb2.y, sb2.y);
        const float* w2p = sm + W2T_OFF + tx * 68 + j * 8;
        ulonglong2 q0 = *(const ulonglong2*)(w2p);
        ulonglong2 q1 = *(const ulonglong2*)(w2p + 4);
        #pragma unroll
        for (int p = 0; p < 4; p++) {
            u64 h2 = bb;
            ffma2(h2, acc[p][j], s2);
            float h0, h1; upk2(h2, h0, h1);
            h0 = fmaxf(h0, 0.f); h1 = fmaxf(h1, 0.f);
            u64 h0b = pk2(h0, h0), h1b = pk2(h1, h1);
            int r0i = (2 * p) * 4, r1i = (2 * p + 1) * 4;
            ffma2(v[r0i + 0], h0b, q0.x);
            ffma2(v[r0i + 1], h0b, q0.y);
            ffma2(v[r0i + 2], h0b, q1.x);
            ffma2(v[r0i + 3], h0b, q1.y);
            ffma2(v[r1i + 0], h1b, q0.x);
            ffma2(v[r1i + 1], h1b, q0.y);
            ffma2(v[r1i + 2], h1b, q1.x);
            ffma2(v[r1i + 3], h1b, q1.y);
        }
    }

    // ---- select-exchange tree reduce over 16 tx lanes ----
    // round 1 (xor 8): keep 4 rows
    {
        bool hi = (tx & 8) != 0;
        #pragma unroll
        for (int i = 0; i < 16; i++) {
            u64 mine  = hi ? v[16 + i] : v[i];
            u64 other = hi ? v[i] : v[16 + i];
            v[i] = add2(mine, __shfl_xor_sync(0xffffffffu, other, 8));
        }
    }
    // round 2 (xor 4): keep 2 rows
    {
        bool hi = (tx & 4) != 0;
        #pragma unroll
        for (int i = 0; i < 8; i++) {
            u64 mine  = hi ? v[8 + i] : v[i];
            u64 other = hi ? v[i] : v[8 + i];
            v[i] = add2(mine, __shfl_xor_sync(0xffffffffu, other, 4));
        }
    }
    // round 3 (xor 2): keep 1 row
    {
        bool hi = (tx & 2) != 0;
        #pragma unroll
        for (int i = 0; i < 4; i++) {
            u64 mine  = hi ? v[4 + i] : v[i];
            u64 other = hi ? v[i] : v[4 + i];
            v[i] = add2(mine, __shfl_xor_sync(0xffffffffu, other, 2));
        }
    }
    // round 4 (xor 1): complete sum, same row on both lanes
    #pragma unroll
    for (int i = 0; i < 4; i++)
        v[i] = add2(v[i], __shfl_xor_sync(0xffffffffu, v[i], 1));

    // lane tx owns row R = 4*b3 + 2*b2 + b1 (duplicated across b0)
    if ((tx & 1) == 0) {
        int R = ((tx >> 3) & 1) * 4 + ((tx >> 2) & 1) * 2 + ((tx >> 1) & 1);
        int lrow = ty * 8 + R;
        int grow = row0 + lrow;

        ulonglong2 b2a = *(const ulonglong2*)(sm + B2S_OFF);
        ulonglong2 b2b = *(const ulonglong2*)(sm + B2S_OFF + 4);
        u64 l0 = add2(v[0], b2a.x);
        u64 l1 = add2(v[1], b2a.y);
        u64 l2 = add2(v[2], b2b.x);
        u64 l3 = add2(v[3], b2b.y);
        float lf[8];
        upk2(l0, lf[0], lf[1]); upk2(l1, lf[2], lf[3]);
        upk2(l2, lf[4], lf[5]); upk2(l3, lf[6], lf[7]);
        int best = 0; float bv = lf[0];
        #pragma unroll
        for (int e = 1; e < 8; e++) if (lf[e] > bv) { bv = lf[e]; best = e; }

        float rr[8];
        #pragma unroll
        for (int e = 0; e < 8; e++) rr[e] = (e == best) ? 1.0f : 0.0f;
        float4* pr = (float4*)(ret + (size_t)grow * EE);
        pr[0] = make_float4(rr[0], rr[1], rr[2], rr[3]);
        pr[1] = make_float4(rr[4], rr[5], rr[6], rr[7]);

        best_s[lrow] = best;
    }
    __syncthreads();

    // ================= expert GEMV: 2 threads per row =================
    {
        int lrow = tid >> 1;
        int half = tid & 1;
        int grow = row0 + lrow;
        int best = best_s[lrow];

        // x column from Xs
        u64 xp[32];
        const float* xc = sm + XS_OFF + lrow;
        #pragma unroll
        for (int i = 0; i < 32; i++)
            xp[i] = pk2(xc[(2 * i) * XS_KSTR], xc[(2 * i + 1) * XS_KSTR]);

        const float* wep = sm + WES_OFF + best * WE_E_STRIDE;
        float* orow = out + (size_t)grow * AA;
        int aStart = half * 9;

        #pragma unroll
        for (int ai = 0; ai < 9; ai++) {
            int a = aStart + ai;
            const ulonglong2* pw = (const ulonglong2*)(wep + a * WE_A_STRIDE);
            u64 a0 = Z, a1 = Z, a2 = Z, a3 = Z;
            #pragma unroll
            for (int m = 0; m < 8; m++) {
                ulonglong2 q0 = pw[2 * m];
                ulonglong2 q1 = pw[2 * m + 1];
                ffma2(a0, q0.x, xp[4 * m + 0]);
                ffma2(a1, q0.y, xp[4 * m + 1]);
                ffma2(a2, q1.x, xp[4 * m + 2]);
                ffma2(a3, q1.y, xp[4 * m + 3]);
            }
            u64 s = add2(add2(a0, a1), add2(a2, a3));
            float lo, hi; upk2(s, lo, hi);
            orow[a] = lo + hi;
        }
    }
}

extern "C" void kernel_launch(void* const* d_in, const int* in_sizes, int n_in,
                              void* d_out, int out_size) {
    const float* X     = (const float*)d_in[0];
    const float* W1    = (const float*)d_in[1];
    const float* b1    = (const float*)d_in[2];
    const float* gamma = (const float*)d_in[3];
    const float* beta  = (const float*)d_in[4];
    const float* rmean = (const float*)d_in[5];
    const float* rvar  = (const float*)d_in[6];
    const float* W2    = (const float*)d_in[7];
    const float* b2    = (const float*)d_in[8];
    const float* We    = (const float*)d_in[9];

    float* out = (float*)d_out;                    // [N, A]
    float* ret = out + (size_t)NN * AA;            // [N, E]

    size_t smem = SMEM_FLOATS * sizeof(float);
    static bool attr_set = false;
    if (!attr_set) {
        cudaFuncSetAttribute(moe_fused, cudaFuncAttributeMaxDynamicSharedMemorySize, (int)smem);
        attr_set = true;
    }
    moe_fused<<<GRID, 256, smem>>>(X, W1, b1, gamma, beta, rmean, rvar, W2, b2, We, out, ret);
}

// round 5
// speedup vs baseline: 2.5520x; 2.1257x over previous
#include <cuda_runtime.h>

#define NN 524288
#define ROWS_PB 256
#define GRID (NN / ROWS_PB)   // 2048 blocks, 128 threads each, 2 rows/thread
#define DD 64
#define HH 128
#define EE 8
#define AA 18
#define BN_EPS 1e-5f

typedef unsigned long long u64;

__device__ __forceinline__ u64 pk2(float lo, float hi) {
    u64 r; asm("mov.b64 %0,{%1,%2};" : "=l"(r) : "f"(lo), "f"(hi)); return r;
}
__device__ __forceinline__ void upk2(u64 v, float& lo, float& hi) {
    asm("mov.b64 {%0,%1},%2;" : "=f"(lo), "=f"(hi) : "l"(v));
}
__device__ __forceinline__ void ffma2(u64& d, u64 a, u64 b) {
    asm("fma.rn.f32x2 %0,%1,%2,%0;" : "+l"(d) : "l"(a), "l"(b));
}
__device__ __forceinline__ u64 add2(u64 a, u64 b) {
    u64 r; asm("add.rn.f32x2 %0,%1,%2;" : "=l"(r) : "l"(a), "l"(b)); return r;
}

// smem layout (floats):
//   w1s [0, 8192)        W1 row-major [H][D]  (uniform broadcast reads)
//   w2t [8192, 9216)     W2 transposed [H][E]
//   sbs [9216, 9472)     (scale,bias) interleaved per j
//   b2s [9472, 9488)
//   wes [9488, ...)      We flat, stride 1156/expert
#define WE_STRIDE 1156
#define SMEM_FLOATS (9488 + EE * WE_STRIDE)

__global__ __launch_bounds__(128, 2) void moe_fused(
    const float* __restrict__ X,  const float* __restrict__ W1, const float* __restrict__ b1,
    const float* __restrict__ gamma, const float* __restrict__ beta,
    const float* __restrict__ rmean, const float* __restrict__ rvar,
    const float* __restrict__ W2, const float* __restrict__ b2, const float* __restrict__ We,
    float* __restrict__ out, float* __restrict__ ret)
{
    extern __shared__ float sm[];
    float* w1s = sm;
    float* w2t = sm + 8192;
    float* sbs = sm + 9216;
    float* b2s = sm + 9472;
    float* wes = sm + 9488;

    const int tid = threadIdx.x;

    // ---- stage weights (128 threads) ----
    {   // W1: 2048 float4 linear copy
        const float4* src = (const float4*)W1;
        float4* dst = (float4*)w1s;
        #pragma unroll
        for (int i = 0; i < 16; i++) dst[tid + 128 * i] = src[tid + 128 * i];
    }
    {   // We: 8 x 288 float4, dst stride 289 float4
        const float4* src = (const float4*)We;
        float4* dst = (float4*)wes;
        #pragma unroll
        for (int i = 0; i < 18; i++) {
            int idx = tid + 128 * i;   // < 2304
            int e = idx / 288, r = idx % 288;
            dst[e * (WE_STRIDE / 4) + r] = src[idx];
        }
    }
    #pragma unroll
    for (int i = 0; i < 8; i++) {   // w2t[j*8+e] = W2[e*H+j]
        int idx = tid + 128 * i;
        int j = idx >> 3, e = idx & 7;
        w2t[idx] = W2[e * HH + j];
    }
    {
        int j = tid;
        float s = gamma[j] * rsqrtf(rvar[j] + BN_EPS);
        sbs[2 * j]     = s;
        sbs[2 * j + 1] = s * (b1[j] - rmean[j]) + beta[j];
    }
    if (tid < EE) b2s[tid] = b2[tid];
    __syncthreads();

    const int r0 = blockIdx.x * ROWS_PB + tid;
    const int r1 = r0 + 128;

    // ---- x for both rows, k-packed f32x2 ----
    u64 xp0[32], xp1[32];
    {
        const ulonglong2* p0 = (const ulonglong2*)(X + (size_t)r0 * DD);
        const ulonglong2* p1 = (const ulonglong2*)(X + (size_t)r1 * DD);
        #pragma unroll
        for (int i = 0; i < 16; i++) {
            ulonglong2 t0 = p0[i]; xp0[2 * i] = t0.x; xp0[2 * i + 1] = t0.y;
            ulonglong2 t1 = p1[i]; xp1[2 * i] = t1.x; xp1[2 * i + 1] = t1.y;
        }
    }

    const u64 Z = pk2(0.f, 0.f);

    u64 lg0[4], lg1[4];
    #pragma unroll
    for (int k = 0; k < 4; k++) {
        u64 b2p = pk2(b2s[2 * k], b2s[2 * k + 1]);
        lg0[k] = b2p; lg1[k] = b2p;
    }

    // ---- gating: shared W1 loads serve both rows ----
    #pragma unroll 2
    for (int j = 0; j < HH; j++) {
        const ulonglong2* pw = (const ulonglong2*)(w1s + j * DD);
        u64 a0 = Z, a1 = Z, a2 = Z, a3 = Z;
        u64 c0 = Z, c1 = Z, c2 = Z, c3 = Z;
        #pragma unroll
        for (int i = 0; i < 8; i++) {
            ulonglong2 w = pw[2 * i];      // floats [8i, 8i+4)
            ulonglong2 v = pw[2 * i + 1];  // floats [8i+4, 8i+8)
            ffma2(a0, w.x, xp0[4 * i + 0]);
            ffma2(c0, w.x, xp1[4 * i + 0]);
            ffma2(a1, w.y, xp0[4 * i + 1]);
            ffma2(c1, w.y, xp1[4 * i + 1]);
            ffma2(a2, v.x, xp0[4 * i + 2]);
            ffma2(c2, v.x, xp1[4 * i + 2]);
            ffma2(a3, v.y, xp0[4 * i + 3]);
            ffma2(c3, v.y, xp1[4 * i + 3]);
        }
        u64 s0 = add2(add2(a0, a1), add2(a2, a3));
        u64 s1 = add2(add2(c0, c1), add2(c2, c3));
        float l0, h0, l1, h1;
        upk2(s0, l0, h0); upk2(s1, l1, h1);
        float dot0 = l0 + h0, dot1 = l1 + h1;

        float2 sb = ((const float2*)sbs)[j];
        float y0 = fmaxf(fmaf(sb.x, dot0, sb.y), 0.f);
        float y1 = fmaxf(fmaf(sb.x, dot1, sb.y), 0.f);
        u64 yb0 = pk2(y0, y0), yb1 = pk2(y1, y1);

        const ulonglong2* pw2 = (const ulonglong2*)(w2t + j * EE);
        ulonglong2 q0 = pw2[0], q1 = pw2[1];
        ffma2(lg0[0], q0.x, yb0);
        ffma2(lg1[0], q0.x, yb1);
        ffma2(lg0[1], q0.y, yb0);
        ffma2(lg1[1], q0.y, yb1);
        ffma2(lg0[2], q1.x, yb0);
        ffma2(lg1[2], q1.x, yb1);
        ffma2(lg0[3], q1.y, yb0);
        ffma2(lg1[3], q1.y, yb1);
    }

    // ---- argmax + one-hot + expert GEMV, per row ----
    #pragma unroll
    for (int rr = 0; rr < 2; rr++) {
        const u64* lg  = rr ? lg1 : lg0;
        const u64* xp  = rr ? xp1 : xp0;
        const int row  = rr ? r1 : r0;

        float lf[8];
        upk2(lg[0], lf[0], lf[1]);
        upk2(lg[1], lf[2], lf[3]);
        upk2(lg[2], lf[4], lf[5]);
        upk2(lg[3], lf[6], lf[7]);
        int best = 0; float bv = lf[0];
        #pragma unroll
        for (int e = 1; e < 8; e++) if (lf[e] > bv) { bv = lf[e]; best = e; }

        float rv[8];
        #pragma unroll
        for (int e = 0; e < 8; e++) rv[e] = (e == best) ? 1.0f : 0.0f;
        float4* pr = (float4*)(ret + (size_t)row * EE);
        pr[0] = make_float4(rv[0], rv[1], rv[2], rv[3]);
        pr[1] = make_float4(rv[4], rv[5], rv[6], rv[7]);

        const ulonglong2* pe = (const ulonglong2*)(wes + best * WE_STRIDE);
        float* orow = out + (size_t)row * AA;
        #pragma unroll
        for (int a = 0; a < AA; a++) {
            u64 a0 = Z, a1 = Z, a2 = Z, a3 = Z;
            #pragma unroll
            for (int m = 0; m < 8; m++) {
                ulonglong2 w = pe[a * 16 + 2 * m];
                ulonglong2 v = pe[a * 16 + 2 * m + 1];
                ffma2(a0, w.x, xp[4 * m + 0]);
                ffma2(a1, w.y, xp[4 * m + 1]);
                ffma2(a2, v.x, xp[4 * m + 2]);
                ffma2(a3, v.y, xp[4 * m + 3]);
            }
            u64 s = add2(add2(a0, a1), add2(a2, a3));
            float lo, hi; upk2(s, lo, hi);
            orow[a] = lo + hi;
        }
    }
}

extern "C" void kernel_launch(void* const* d_in, const int* in_sizes, int n_in,
                              void* d_out, int out_size) {
    const float* X     = (const float*)d_in[0];
    const float* W1    = (const float*)d_in[1];
    const float* b1    = (const float*)d_in[2];
    const float* gamma = (const float*)d_in[3];
    const float* beta  = (const float*)d_in[4];
    const float* rmean = (const float*)d_in[5];
    const float* rvar  = (const float*)d_in[6];
    const float* W2    = (const float*)d_in[7];
    const float* b2    = (const float*)d_in[8];
    const float* We    = (const float*)d_in[9];

    float* out = (float*)d_out;                    // [N, A]
    float* ret = out + (size_t)NN * AA;            // [N, E]

    size_t smem = SMEM_FLOATS * sizeof(float);
    static bool attr_set = false;
    if (!attr_set) {
        cudaFuncSetAttribute(moe_fused, cudaFuncAttributeMaxDynamicSharedMemorySize, (int)smem);
        attr_set = true;
    }
    moe_fused<<<GRID, 128, smem>>>(X, W1, b1, gamma, beta, rmean, rvar, W2, b2, We, out, ret);
}

// round 6
// speedup vs baseline: 2.7767x; 1.0880x over previous
#include <cuda_runtime.h>

#define NN 524288
#define ROWS_PB 384
#define GRID ((NN + ROWS_PB - 1) / ROWS_PB)   // 1366
#define DD 64
#define HH 128
#define EE 8
#define AA 18
#define BN_EPS 1e-5f

typedef unsigned long long u64;

__device__ __forceinline__ u64 pk2(float lo, float hi) {
    u64 r; asm("mov.b64 %0,{%1,%2};" : "=l"(r) : "f"(lo), "f"(hi)); return r;
}
__device__ __forceinline__ void upk2(u64 v, float& lo, float& hi) {
    asm("mov.b64 {%0,%1},%2;" : "=f"(lo), "=f"(hi) : "l"(v));
}
__device__ __forceinline__ void ffma2(u64& d, u64 a, u64 b) {
    asm("fma.rn.f32x2 %0,%1,%2,%0;" : "+l"(d) : "l"(a), "l"(b));
}
__device__ __forceinline__ u64 add2(u64 a, u64 b) {
    u64 r; asm("add.rn.f32x2 %0,%1,%2;" : "=l"(r) : "l"(a), "l"(b)); return r;
}

// smem layout (floats):
//   w1s [0, 8192)        W1 row-major [H][D]
//   w2t [8192, 9216)     W2 transposed [H][E]
//   sbs [9216, 9472)     (scale,bias) interleaved per j
//   b2s [9472, 9488)
//   wes [9488, ...)      We flat, stride 1156/expert
#define WE_STRIDE 1156
#define SMEM_FLOATS (9488 + EE * WE_STRIDE)

__global__ __launch_bounds__(128, 2) void moe_fused(
    const float* __restrict__ X,  const float* __restrict__ W1, const float* __restrict__ b1,
    const float* __restrict__ gamma, const float* __restrict__ beta,
    const float* __restrict__ rmean, const float* __restrict__ rvar,
    const float* __restrict__ W2, const float* __restrict__ b2, const float* __restrict__ We,
    float* __restrict__ out, float* __restrict__ ret)
{
    extern __shared__ float sm[];
    float* w1s = sm;
    float* w2t = sm + 8192;
    float* sbs = sm + 9216;
    float* b2s = sm + 9472;
    float* wes = sm + 9488;

    const int tid = threadIdx.x;

    // ---- stage weights (128 threads) ----
    {   // W1: 2048 float4 linear copy
        const float4* src = (const float4*)W1;
        float4* dst = (float4*)w1s;
        #pragma unroll
        for (int i = 0; i < 16; i++) dst[tid + 128 * i] = src[tid + 128 * i];
    }
    {   // We: 8 x 288 float4, dst stride 289 float4
        const float4* src = (const float4*)We;
        float4* dst = (float4*)wes;
        #pragma unroll
        for (int i = 0; i < 18; i++) {
            int idx = tid + 128 * i;   // < 2304
            int e = idx / 288, r = idx % 288;
            dst[e * (WE_STRIDE / 4) + r] = src[idx];
        }
    }
    #pragma unroll
    for (int i = 0; i < 8; i++) {   // w2t[j*8+e] = W2[e*H+j]
        int idx = tid + 128 * i;
        int j = idx >> 3, e = idx & 7;
        w2t[idx] = W2[e * HH + j];
    }
    {
        int j = tid;
        float s = gamma[j] * rsqrtf(rvar[j] + BN_EPS);
        sbs[2 * j]     = s;
        sbs[2 * j + 1] = s * (b1[j] - rmean[j]) + beta[j];
    }
    if (tid < EE) b2s[tid] = b2[tid];
    __syncthreads();

    const int base = blockIdx.x * ROWS_PB + tid;
    int rowi[3];
    bool valid[3];
    #pragma unroll
    for (int rr = 0; rr < 3; rr++) {
        int r = base + rr * 128;
        valid[rr] = (r < NN);
        rowi[rr] = valid[rr] ? r : (NN - 1);
    }

    // ---- x for 3 rows, k-packed f32x2 (96 u64 = 192 regs) ----
    u64 xp0[32], xp1[32], xp2[32];
    {
        const ulonglong2* p0 = (const ulonglong2*)(X + (size_t)rowi[0] * DD);
        const ulonglong2* p1 = (const ulonglong2*)(X + (size_t)rowi[1] * DD);
        const ulonglong2* p2 = (const ulonglong2*)(X + (size_t)rowi[2] * DD);
        #pragma unroll
        for (int i = 0; i < 16; i++) {
            ulonglong2 t0 = p0[i]; xp0[2 * i] = t0.x; xp0[2 * i + 1] = t0.y;
            ulonglong2 t1 = p1[i]; xp1[2 * i] = t1.x; xp1[2 * i + 1] = t1.y;
            ulonglong2 t2 = p2[i]; xp2[2 * i] = t2.x; xp2[2 * i + 1] = t2.y;
        }
    }

    const u64 Z = pk2(0.f, 0.f);

    u64 lg0[4], lg1[4], lg2[4];
    #pragma unroll
    for (int k = 0; k < 4; k++) {
        u64 b2p = pk2(b2s[2 * k], b2s[2 * k + 1]);
        lg0[k] = b2p; lg1[k] = b2p; lg2[k] = b2p;
    }

    // ---- gating: each uniform W1 load feeds 3 rows ----
    #pragma unroll 1
    for (int j = 0; j < HH; j++) {
        const ulonglong2* pw = (const ulonglong2*)(w1s + j * DD);
        u64 a0 = Z, a1 = Z;        // row 0 accums
        u64 c0 = Z, c1 = Z;        // row 1
        u64 d0 = Z, d1 = Z;        // row 2
        #pragma unroll
        for (int i = 0; i < 16; i++) {
            ulonglong2 w = pw[i];            // floats [4i, 4i+4)
            ffma2(a0, w.x, xp0[2 * i]);
            ffma2(c0, w.x, xp1[2 * i]);
            ffma2(d0, w.x, xp2[2 * i]);
            ffma2(a1, w.y, xp0[2 * i + 1]);
            ffma2(c1, w.y, xp1[2 * i + 1]);
            ffma2(d1, w.y, xp2[2 * i + 1]);
        }
        u64 s0 = add2(a0, a1);
        u64 s1 = add2(c0, c1);
        u64 s2 = add2(d0, d1);
        float e0, f0, e1, f1, e2, f2;
        upk2(s0, e0, f0); upk2(s1, e1, f1); upk2(s2, e2, f2);
        float dot0 = e0 + f0, dot1 = e1 + f1, dot2 = e2 + f2;

        float2 sb = ((const float2*)sbs)[j];
        float y0 = fmaxf(fmaf(sb.x, dot0, sb.y), 0.f);
        float y1 = fmaxf(fmaf(sb.x, dot1, sb.y), 0.f);
        float y2 = fmaxf(fmaf(sb.x, dot2, sb.y), 0.f);
        u64 yb0 = pk2(y0, y0), yb1 = pk2(y1, y1), yb2 = pk2(y2, y2);

        const ulonglong2* pw2 = (const ulonglong2*)(w2t + j * EE);
        ulonglong2 q0 = pw2[0], q1 = pw2[1];
        ffma2(lg0[0], q0.x, yb0);
        ffma2(lg1[0], q0.x, yb1);
        ffma2(lg2[0], q0.x, yb2);
        ffma2(lg0[1], q0.y, yb0);
        ffma2(lg1[1], q0.y, yb1);
        ffma2(lg2[1], q0.y, yb2);
        ffma2(lg0[2], q1.x, yb0);
        ffma2(lg1[2], q1.x, yb1);
        ffma2(lg2[2], q1.x, yb2);
        ffma2(lg0[3], q1.y, yb0);
        ffma2(lg1[3], q1.y, yb1);
        ffma2(lg2[3], q1.y, yb2);
    }

    // ---- per row: argmax + one-hot + expert GEMV ----
    #pragma unroll 1
    for (int rr = 0; rr < 3; rr++) {
        if (!valid[rr]) continue;
        const u64* lg = (rr == 0) ? lg0 : (rr == 1) ? lg1 : lg2;
        const u64* xp = (rr == 0) ? xp0 : (rr == 1) ? xp1 : xp2;
        const int row = rowi[rr];

        float lf[8];
        upk2(lg[0], lf[0], lf[1]);
        upk2(lg[1], lf[2], lf[3]);
        upk2(lg[2], lf[4], lf[5]);
        upk2(lg[3], lf[6], lf[7]);
        int best = 0; float bv = lf[0];
        #pragma unroll
        for (int e = 1; e < 8; e++) if (lf[e] > bv) { bv = lf[e]; best = e; }

        float rv[8];
        #pragma unroll
        for (int e = 0; e < 8; e++) rv[e] = (e == best) ? 1.0f : 0.0f;
        float4* pr = (float4*)(ret + (size_t)row * EE);
        pr[0] = make_float4(rv[0], rv[1], rv[2], rv[3]);
        pr[1] = make_float4(rv[4], rv[5], rv[6], rv[7]);

        const ulonglong2* pe = (const ulonglong2*)(wes + best * WE_STRIDE);
        float* orow = out + (size_t)row * AA;
        #pragma unroll
        for (int a = 0; a < AA; a++) {
            u64 a0 = Z, a1 = Z, a2 = Z, a3 = Z;
            #pragma unroll
            for (int m = 0; m < 8; m++) {
                ulonglong2 w = pe[a * 16 + 2 * m];
                ulonglong2 v = pe[a * 16 + 2 * m + 1];
                ffma2(a0, w.x, xp[4 * m + 0]);
                ffma2(a1, w.y, xp[4 * m + 1]);
                ffma2(a2, v.x, xp[4 * m + 2]);
                ffma2(a3, v.y, xp[4 * m + 3]);
            }
            u64 s = add2(add2(a0, a1), add2(a2, a3));
            float lo, hi; upk2(s, lo, hi);
            orow[a] = lo + hi;
        }
    }
}

extern "C" void kernel_launch(void* const* d_in, const int* in_sizes, int n_in,
                              void* d_out, int out_size) {
    const float* X     = (const float*)d_in[0];
    const float* W1    = (const float*)d_in[1];
    const float* b1    = (const float*)d_in[2];
    const float* gamma = (const float*)d_in[3];
    const float* beta  = (const float*)d_in[4];
    const float* rmean = (const float*)d_in[5];
    const float* rvar  = (const float*)d_in[6];
    const float* W2    = (const float*)d_in[7];
    const float* b2    = (const float*)d_in[8];
    const float* We    = (const float*)d_in[9];

    float* out = (float*)d_out;                    // [N, A]
    float* ret = out + (size_t)NN * AA;            // [N, E]

    size_t smem = SMEM_FLOATS * sizeof(float);
    static bool attr_set = false;
    if (!attr_set) {
        cudaFuncSetAttribute(moe_fused, cudaFuncAttributeMaxDynamicSharedMemorySize, (int)smem);
        attr_set = true;
    }
    moe_fused<<<GRID, 128, smem>>>(X, W1, b1, gamma, beta, rmean, rvar, W2, b2, We, out, ret);
}